// round 11
// baseline (speedup 1.0000x reference)
#include <cuda_runtime.h>
#include <cstdint>
#include <cstddef>

// Scatter-mean message passing via single-pass padded-CSR build + per-node gather-reduce.
//   out[t] = mean over edges e with tgt[e]==t of x[src[e]]
// x: [N, 64] f32, edge_idx: [2, E] i32 (row 0 = src, row 1 = tgt)

#define F 64
#define MAX_N (1 << 17)      // >= 100000
#define SLOTS 32             // padded CSR row capacity = 128B = one L2 line
#define MAX_OVER 16384       // overflow spill capacity (correctness fallback)
#define AGG_BLOCKS (148 * 8) // persistent grid: one wave at occ 8

typedef unsigned long long ull;

__device__ int g_cnt[MAX_N];                     // per-node edge count (true degree)
__device__ int g_sorted[(size_t)MAX_N * SLOTS];  // per-node src BYTE OFFSETS (src*256)
__device__ int g_over_src[MAX_OVER];             // overflow: src byte offsets
__device__ int g_over_tgt[MAX_OVER];
__device__ int g_over_cnt[1];

__device__ __forceinline__ void spill_edge(int soff, int d) {
    int op = atomicAdd(&g_over_cnt[0], 1);
    if (op < MAX_OVER) { g_over_src[op] = soff; g_over_tgt[op] = d; }
}

// Single build pass: 8 edges per thread (2x int4). All 8 atomics issued
// back-to-back (8 ATOMG round-trips in flight), then all 8 scattered stores.
__global__ void fill_kernel(const int4* __restrict__ src4,
                            const int4* __restrict__ tgt4, int E8,
                            const int* __restrict__ src,
                            const int* __restrict__ tgt, int E) {
    int t = blockIdx.x * blockDim.x + threadIdx.x;
    if (t < E8) {
        int4 sA = __ldg(&src4[2 * t]);
        int4 sB = __ldg(&src4[2 * t + 1]);
        int4 dA = __ldg(&tgt4[2 * t]);
        int4 dB = __ldg(&tgt4[2 * t + 1]);
        int p0 = atomicAdd(&g_cnt[dA.x], 1);
        int p1 = atomicAdd(&g_cnt[dA.y], 1);
        int p2 = atomicAdd(&g_cnt[dA.z], 1);
        int p3 = atomicAdd(&g_cnt[dA.w], 1);
        int p4 = atomicAdd(&g_cnt[dB.x], 1);
        int p5 = atomicAdd(&g_cnt[dB.y], 1);
        int p6 = atomicAdd(&g_cnt[dB.z], 1);
        int p7 = atomicAdd(&g_cnt[dB.w], 1);
        if (p0 < SLOTS) g_sorted[(size_t)dA.x * SLOTS + p0] = sA.x << 8; else spill_edge(sA.x << 8, dA.x);
        if (p1 < SLOTS) g_sorted[(size_t)dA.y * SLOTS + p1] = sA.y << 8; else spill_edge(sA.y << 8, dA.y);
        if (p2 < SLOTS) g_sorted[(size_t)dA.z * SLOTS + p2] = sA.z << 8; else spill_edge(sA.z << 8, dA.z);
        if (p3 < SLOTS) g_sorted[(size_t)dA.w * SLOTS + p3] = sA.w << 8; else spill_edge(sA.w << 8, dA.w);
        if (p4 < SLOTS) g_sorted[(size_t)dB.x * SLOTS + p4] = sB.x << 8; else spill_edge(sB.x << 8, dB.x);
        if (p5 < SLOTS) g_sorted[(size_t)dB.y * SLOTS + p5] = sB.y << 8; else spill_edge(sB.y << 8, dB.y);
        if (p6 < SLOTS) g_sorted[(size_t)dB.z * SLOTS + p6] = sB.z << 8; else spill_edge(sB.z << 8, dB.z);
        if (p7 < SLOTS) g_sorted[(size_t)dB.w * SLOTS + p7] = sB.w << 8; else spill_edge(sB.w << 8, dB.w);
    }
    if (t == 0) {
        for (int e = E8 * 8; e < E; e++) {
            int d = tgt[e];
            int pos = atomicAdd(&g_cnt[d], 1);
            if (pos < SLOTS) g_sorted[(size_t)d * SLOTS + pos] = src[e] << 8;
            else spill_edge(src[e] << 8, d);
        }
    }
}

__device__ __forceinline__ ull f2add(ull a, ull b) {
    ull r;
    asm("add.rn.f32x2 %0, %1, %2;" : "=l"(r) : "l"(a), "l"(b));
    return r;
}
__device__ __forceinline__ ull f2mul(ull a, ull b) {
    ull r;
    asm("mul.rn.f32x2 %0, %1, %2;" : "=l"(r) : "l"(a), "l"(b));
    return r;
}
// L2-only gather (skip L1 allocation: gathered rows have ~no per-SM reuse).
__device__ __forceinline__ ull ldg_cg64(const void* p) {
    ull r;
    asm volatile("ld.global.cg.u64 %0, [%1];" : "=l"(r) : "l"(p));
    return r;
}

// One warp per node, persistent grid-stride over nodes (one wave). Lane owns
// 8B (float2) of the 256B row. Unroll 2, scalar warp-uniform idx loads,
// 2 accumulators (measured optimum vs L1tex queue contention).
__global__ void __launch_bounds__(256)
aggregate_kernel(const char* __restrict__ xbase,
                 float2* __restrict__ out2, int N) {
    int warp_id = (blockIdx.x * blockDim.x + threadIdx.x) >> 5;
    int lane = threadIdx.x & 31;
    int nwarps = (gridDim.x * blockDim.x) >> 5;
    const char* xlane = xbase + (lane << 3);

    for (int n = warp_id; n < N; n += nwarps) {
        int count = g_cnt[n];
        int m = count < SLOTS ? count : SLOTS;
        const int* row = &g_sorted[(size_t)n * SLOTS];

        ull a0 = 0, a1 = 0;

        int k = 0;
        for (; k + 2 <= m; k += 2) {
            int s0 = __ldg(&row[k + 0]);
            int s1 = __ldg(&row[k + 1]);
            ull v0 = ldg_cg64(xlane + (size_t)(unsigned)s0);
            ull v1 = ldg_cg64(xlane + (size_t)(unsigned)s1);
            a0 = f2add(a0, v0);
            a1 = f2add(a1, v1);
        }
        if (k < m) {
            int s = __ldg(&row[k]);
            a0 = f2add(a0, ldg_cg64(xlane + (size_t)(unsigned)s));
        }

        // Overflow fallback (cold: only if some node's degree exceeded SLOTS).
        if (count > SLOTS) {
            int oc = g_over_cnt[0];
            for (int i = 0; i < oc; i++) {
                if (g_over_tgt[i] == n) {
                    int s = g_over_src[i];
                    a0 = f2add(a0, ldg_cg64(xlane + (size_t)(unsigned)s));
                }
            }
        }

        a0 = f2add(a0, a1);

        float inv = count > 0 ? 1.0f / (float)count : 0.0f;
        ull inv2;
        asm("mov.b64 %0, {%1, %1};" : "=l"(inv2) : "f"(inv));
        ull o = f2mul(a0, inv2);

        unsigned int lo, hi;
        asm("mov.b64 {%0, %1}, %2;" : "=r"(lo), "=r"(hi) : "l"(o));
        float2 ov;
        ov.x = __uint_as_float(lo);
        ov.y = __uint_as_float(hi);
        out2[(size_t)n * 32 + lane] = ov;
    }
}

extern "C" void kernel_launch(void* const* d_in, const int* in_sizes, int n_in,
                              void* d_out, int out_size) {
    const float* x = (const float*)d_in[0];
    const int* edge_idx = (const int*)d_in[1];

    int E = in_sizes[1] / 2;
    int N = out_size / F;

    const int* src = edge_idx;       // row 0
    const int* tgt = edge_idx + E;   // row 1

    // Zero scratch counters via memset nodes.
    void* cnt_ptr = nullptr;
    void* over_ptr = nullptr;
    cudaGetSymbolAddress(&cnt_ptr, g_cnt);
    cudaGetSymbolAddress(&over_ptr, g_over_cnt);
    cudaMemsetAsync(cnt_ptr, 0, (size_t)N * sizeof(int));
    cudaMemsetAsync(over_ptr, 0, sizeof(int));

    const int T = 256;

    int E8 = E / 8;
    int fill_blocks = (E8 + T - 1) / T;
    if (fill_blocks < 1) fill_blocks = 1;
    fill_kernel<<<fill_blocks, T>>>((const int4*)src, (const int4*)tgt, E8,
                                    src, tgt, E);

    // Persistent one-wave grid (cap at what N needs).
    long long warps_needed = (long long)N;
    long long blocks_needed = (warps_needed * 32 + T - 1) / T;
    int agg_blocks = blocks_needed < AGG_BLOCKS ? (int)blocks_needed : AGG_BLOCKS;
    aggregate_kernel<<<agg_blocks, T>>>((const char*)x, (float2*)d_out, N);
}

// round 12
// speedup vs baseline: 1.0653x; 1.0653x over previous
#include <cuda_runtime.h>
#include <cstdint>
#include <cstddef>

// Scatter-mean message passing via single-pass padded-CSR build + per-node gather-reduce.
//   out[t] = mean over edges e with tgt[e]==t of x[src[e]]
// x: [N, 64] f32, edge_idx: [2, E] i32 (row 0 = src, row 1 = tgt)

#define F 64
#define MAX_N (1 << 17)      // >= 100000
#define SLOTS 32             // padded CSR row capacity = 128B = one L2 line
#define MAX_OVER 16384       // overflow spill capacity (correctness fallback)
#define AGG_BLOCKS (148 * 8) // persistent grid: one wave at occ 8

typedef unsigned long long ull;

__device__ int g_cnt[MAX_N];                     // per-node edge count (true degree)
__device__ int g_sorted[(size_t)MAX_N * SLOTS];  // per-node src BYTE OFFSETS (src*256)
__device__ int g_over_src[MAX_OVER];             // overflow: src byte offsets
__device__ int g_over_tgt[MAX_OVER];
__device__ int g_over_cnt[1];

__device__ __forceinline__ void spill_edge(int soff, int d) {
    int op = atomicAdd(&g_over_cnt[0], 1);
    if (op < MAX_OVER) { g_over_src[op] = soff; g_over_tgt[op] = d; }
}

// Scattered 4B store bypassing L1 (no reuse).
__device__ __forceinline__ void stg_cg32(int* p, int v) {
    asm volatile("st.global.cg.u32 [%0], %1;" :: "l"(p), "r"(v) : "memory");
}

// Single build pass: 2 edges per thread (int2 loads). Max thread count at
// constant total atomic work -> best ATOMG latency interleaving
// (R11 showed 8/thread regresses; 4/thread was ~20us).
__global__ void fill_kernel(const int2* __restrict__ src2,
                            const int2* __restrict__ tgt2, int E2,
                            const int* __restrict__ src,
                            const int* __restrict__ tgt, int E) {
    int t = blockIdx.x * blockDim.x + threadIdx.x;
    if (t < E2) {
        int2 s = __ldg(&src2[t]);
        int2 d = __ldg(&tgt2[t]);
        int p0 = atomicAdd(&g_cnt[d.x], 1);
        int p1 = atomicAdd(&g_cnt[d.y], 1);
        if (p0 < SLOTS) stg_cg32(&g_sorted[(size_t)d.x * SLOTS + p0], s.x << 8);
        else spill_edge(s.x << 8, d.x);
        if (p1 < SLOTS) stg_cg32(&g_sorted[(size_t)d.y * SLOTS + p1], s.y << 8);
        else spill_edge(s.y << 8, d.y);
    }
    if (t == 0) {
        for (int e = E2 * 2; e < E; e++) {
            int d = tgt[e];
            int pos = atomicAdd(&g_cnt[d], 1);
            if (pos < SLOTS) stg_cg32(&g_sorted[(size_t)d * SLOTS + pos], src[e] << 8);
            else spill_edge(src[e] << 8, d);
        }
    }
}

__device__ __forceinline__ ull f2add(ull a, ull b) {
    ull r;
    asm("add.rn.f32x2 %0, %1, %2;" : "=l"(r) : "l"(a), "l"(b));
    return r;
}
__device__ __forceinline__ ull f2mul(ull a, ull b) {
    ull r;
    asm("mul.rn.f32x2 %0, %1, %2;" : "=l"(r) : "l"(a), "l"(b));
    return r;
}
// L2-only gather (skip L1 allocation: gathered rows have ~no per-SM reuse).
__device__ __forceinline__ ull ldg_cg64(const void* p) {
    ull r;
    asm volatile("ld.global.cg.u64 %0, [%1];" : "=l"(r) : "l"(p));
    return r;
}

// One warp per node, persistent grid-stride over nodes (one wave). Lane owns
// 8B (float2) of the 256B row. Unroll 2, scalar warp-uniform idx loads,
// 2 accumulators (measured optimum vs L1tex queue contention).
__global__ void __launch_bounds__(256)
aggregate_kernel(const char* __restrict__ xbase,
                 float2* __restrict__ out2, int N) {
    int warp_id = (blockIdx.x * blockDim.x + threadIdx.x) >> 5;
    int lane = threadIdx.x & 31;
    int nwarps = (gridDim.x * blockDim.x) >> 5;
    const char* xlane = xbase + (lane << 3);

    for (int n = warp_id; n < N; n += nwarps) {
        int count = g_cnt[n];
        int m = count < SLOTS ? count : SLOTS;
        const int* row = &g_sorted[(size_t)n * SLOTS];

        ull a0 = 0, a1 = 0;

        int k = 0;
        for (; k + 2 <= m; k += 2) {
            int s0 = __ldg(&row[k + 0]);
            int s1 = __ldg(&row[k + 1]);
            ull v0 = ldg_cg64(xlane + (size_t)(unsigned)s0);
            ull v1 = ldg_cg64(xlane + (size_t)(unsigned)s1);
            a0 = f2add(a0, v0);
            a1 = f2add(a1, v1);
        }
        if (k < m) {
            int s = __ldg(&row[k]);
            a0 = f2add(a0, ldg_cg64(xlane + (size_t)(unsigned)s));
        }

        // Overflow fallback (cold: only if some node's degree exceeded SLOTS).
        if (count > SLOTS) {
            int oc = g_over_cnt[0];
            for (int i = 0; i < oc; i++) {
                if (g_over_tgt[i] == n) {
                    int s = g_over_src[i];
                    a0 = f2add(a0, ldg_cg64(xlane + (size_t)(unsigned)s));
                }
            }
        }

        a0 = f2add(a0, a1);

        float inv = count > 0 ? 1.0f / (float)count : 0.0f;
        ull inv2;
        asm("mov.b64 %0, {%1, %1};" : "=l"(inv2) : "f"(inv));
        ull o = f2mul(a0, inv2);

        unsigned int lo, hi;
        asm("mov.b64 {%0, %1}, %2;" : "=r"(lo), "=r"(hi) : "l"(o));
        float2 ov;
        ov.x = __uint_as_float(lo);
        ov.y = __uint_as_float(hi);
        out2[(size_t)n * 32 + lane] = ov;
    }
}

extern "C" void kernel_launch(void* const* d_in, const int* in_sizes, int n_in,
                              void* d_out, int out_size) {
    const float* x = (const float*)d_in[0];
    const int* edge_idx = (const int*)d_in[1];

    int E = in_sizes[1] / 2;
    int N = out_size / F;

    const int* src = edge_idx;       // row 0
    const int* tgt = edge_idx + E;   // row 1

    // Zero scratch counters via memset nodes.
    void* cnt_ptr = nullptr;
    void* over_ptr = nullptr;
    cudaGetSymbolAddress(&cnt_ptr, g_cnt);
    cudaGetSymbolAddress(&over_ptr, g_over_cnt);
    cudaMemsetAsync(cnt_ptr, 0, (size_t)N * sizeof(int));
    cudaMemsetAsync(over_ptr, 0, sizeof(int));

    const int T = 256;

    int E2 = E / 2;
    int fill_blocks = (E2 + T - 1) / T;
    if (fill_blocks < 1) fill_blocks = 1;
    fill_kernel<<<fill_blocks, T>>>((const int2*)src, (const int2*)tgt, E2,
                                    src, tgt, E);

    // Persistent one-wave grid (cap at what N needs).
    long long warps_needed = (long long)N;
    long long blocks_needed = (warps_needed * 32 + T - 1) / T;
    int agg_blocks = blocks_needed < AGG_BLOCKS ? (int)blocks_needed : AGG_BLOCKS;
    aggregate_kernel<<<agg_blocks, T>>>((const char*)x, (float2*)d_out, N);
}